// round 6
// baseline (speedup 1.0000x reference)
#include <cuda_runtime.h>

#define B_ 8
#define P_ 10
#define S_ 160
#define FX_ 11
#define D_ 64
#define DFF_ 256
#define NROW (B_*P_*S_)   /* 12800 */
#define NPART (B_*P_)     /* 80 */

/* output layout (tuple order): pred, pred_resampl, K, V, R, attn_weights */
#define OFF_PRED  0
#define OFF_PRED2 (NROW)
#define OFF_K     (2*NROW)
#define OFF_V     (OFF_K + NROW*D_)
#define OFF_R     (OFF_V + NROW*D_)
#define OFF_ATTN  (OFF_R + NROW*D_)

/* scratch (no cudaMalloc allowed) */
__device__ float g_x[NROW*D_];
__device__ float g_q[NROW*D_];
__device__ float g_z[NROW*D_];

typedef unsigned long long u64t;

__device__ __forceinline__ void fma4(float4& acc, float s, const float4& v) {
    acc.x += s * v.x; acc.y += s * v.y; acc.z += s * v.z; acc.w += s * v.w;
}
__device__ __forceinline__ void fma2p(u64t& acc, u64t a, u64t b) {
    asm("fma.rn.f32x2 %0, %1, %2, %0;" : "+l"(acc) : "l"(a), "l"(b));
}
__device__ __forceinline__ u64t dup2(float x) {
    u64t r;
    asm("mov.b64 %0, {%1, %1};" : "=l"(r) : "f"(x));
    return r;
}
__device__ __forceinline__ void unpack2(float& lo, float& hi, u64t v) {
    asm("mov.b64 {%0, %1}, %2;" : "=f"(lo), "=f"(hi) : "l"(v));
}

/* ------------------------------------------------------------------ */
/* K1: fold Wp into W{q,k,v} in-block, then x,q,k,v = in @ fused.     */
/* 100 blocks x 512 thr x 128 rows. Attention scale 1/8 folded in q.  */
/* ------------------------------------------------------------------ */
__global__ void __launch_bounds__(512) k_qkv(
    const float* __restrict__ inp,
    const float* __restrict__ Wp, const float* __restrict__ bp,
    const float* __restrict__ Wq, const float* __restrict__ bq,
    const float* __restrict__ Wk, const float* __restrict__ bk,
    const float* __restrict__ Wv, const float* __restrict__ bv,
    float* __restrict__ outK, float* __restrict__ outV)
{
    extern __shared__ float sm[];
    float* sW  = sm;          /* 2816: fused x,q,k,v weights (11x64 each) */
    float* sB  = sW + 2816;   /* 256 */
    float* sIn = sB + 256;    /* 1408 */
    float* sT  = sIn + 1408;  /* 4096 tmp */
    const int tid = threadIdx.x;
    const int row0 = blockIdx.x * 128;

    /* raw Wp, bp, inputs */
    for (int i = tid; i < 704;  i += 512) sW[i] = Wp[i];
    if (tid < 64) sB[tid] = bp[tid];
    for (int i = tid; i < 1408; i += 512) sIn[i] = inp[(size_t)row0*11 + i];

    /* fold Wq/Wk/Wv */
    #pragma unroll
    for (int b = 1; b <= 3; ++b) {
        const float* W  = (b == 1) ? Wq : (b == 2) ? Wk : Wv;
        const float* bb = (b == 1) ? bq : (b == 2) ? bk : bv;
        const float fw = (b == 1) ? 1.0f   : 8.0f;
        const float fb = (b == 1) ? 0.125f : 1.0f;
        for (int i = tid; i < 4096; i += 512) sT[i] = W[i];
        __syncthreads();
        for (int idx = tid; idx < 704; idx += 512) {
            int ii = idx >> 6, j = idx & 63;
            float s = 0.0f;
            #pragma unroll 4
            for (int d = 0; d < 64; ++d) s += sW[ii*64 + d] * sT[d*64 + j];
            sW[b*704 + idx] = fw * s;
        }
        if (tid < 64) {
            float s = 0.0f;
            for (int d = 0; d < 64; ++d) s += sB[d] * sT[d*64 + tid];
            sB[b*64 + tid] = fw * s + fb * bb[tid];
        }
        __syncthreads();
    }
    /* scale x-path */
    for (int i = tid; i < 704; i += 512) sW[i] *= 8.0f;
    if (tid < 64) sB[tid] *= 8.0f;
    __syncthreads();

    const int j = tid & 63;
    float wx[11], wq[11], wk[11], wv[11];
    #pragma unroll
    for (int i = 0; i < 11; ++i) {
        wx[i] = sW[i*64 + j];
        wq[i] = sW[704  + i*64 + j];
        wk[i] = sW[1408 + i*64 + j];
        wv[i] = sW[2112 + i*64 + j];
    }
    const float bx = sB[j], bqv = sB[64+j], bkv = sB[128+j], bvv = sB[192+j];

    #pragma unroll
    for (int h = 0; h < 2; ++h) {
        const int rb = h*64 + (tid >> 6) * 8;
        float ax[8], aq[8], ak[8], av[8];
        #pragma unroll
        for (int r = 0; r < 8; ++r) { ax[r]=bx; aq[r]=bqv; ak[r]=bkv; av[r]=bvv; }
        #pragma unroll
        for (int i = 0; i < 11; ++i) {
            #pragma unroll
            for (int r = 0; r < 8; ++r) {
                float in = sIn[(rb+r)*11 + i];
                ax[r] += in * wx[i];
                aq[r] += in * wq[i];
                ak[r] += in * wk[i];
                av[r] += in * wv[i];
            }
        }
        #pragma unroll
        for (int r = 0; r < 8; ++r) {
            size_t n = (size_t)(row0 + rb + r) * 64 + j;
            g_x[n]  = ax[r];
            g_q[n]  = aq[r];
            outK[n] = ak[r];
            outV[n] = av[r];
        }
    }
}

/* ------------------------------------------------------------------ */
/* K2: causal attention, causal loop bounds, balanced warp mapping.   */
/* ------------------------------------------------------------------ */
template<int NC>
__device__ __forceinline__ void score_nc(
    const float* __restrict__ sKt, const float* __restrict__ sQ,
    int mbase, int lane, float (&sc)[5][5])
{
    #pragma unroll 2
    for (int i = 0; i < 64; ++i) {
        float kv[NC];
        #pragma unroll
        for (int c = 0; c < NC; ++c) kv[c] = sKt[i*161 + c*32 + lane];
        #pragma unroll
        for (int k = 0; k < 5; ++k) {
            float qi = sQ[(mbase+k)*64 + i];
            #pragma unroll
            for (int c = 0; c < NC; ++c) sc[k][c] += qi * kv[c];
        }
    }
}

__global__ void __launch_bounds__(256) k_attn(
    const float* __restrict__ Kin, const float* __restrict__ Vin,
    float* __restrict__ attnOut)
{
    extern __shared__ float sm[];
    float* sKt = sm;             /* 64 x 161 = 10304; reused as sA (40x160) */
    float* sV  = sKt + 10304;    /* 160 x 64 = 10240 */
    float* sQ  = sV  + 10240;    /* 40 x 64  = 2560  */
    float* sA  = sKt;

    const int tid  = threadIdx.x;
    const int lane = tid & 31;
    const int w    = tid >> 5;
    const int part = blockIdx.x >> 2;
    const int quad = blockIdx.x & 3;
    /* warp -> row-range r; pairs (w, w+4) share SMSP with r sums == 7 */
    const int r    = (w < 4) ? w : 11 - w;
    const int mbase = 5 * r;
    const int tmax  = quad + 20*r + 16;     /* max t in this warp */
    const int nc    = (tmax >> 5) + 1;      /* 32-wide chunks needed */

    const float4* Kg4 = (const float4*)(Kin + (size_t)part*160*64);
    const float4* Vg4 = (const float4*)(Vin + (size_t)part*160*64);
    float4* sV4 = (float4*)sV;

    for (int idx = tid; idx < 160*16; idx += 256) {
        int s = idx >> 4, i4 = (idx & 15) * 4;
        float4 kk = Kg4[idx];
        sKt[(i4+0)*161 + s] = kk.x;
        sKt[(i4+1)*161 + s] = kk.y;
        sKt[(i4+2)*161 + s] = kk.z;
        sKt[(i4+3)*161 + s] = kk.w;
        sV4[idx] = Vg4[idx];
    }
    for (int idx = tid; idx < 40*16; idx += 256) {
        int m = idx >> 4, i4 = idx & 15;
        int row = part*160 + quad + 4*m;
        ((float4*)(sQ + m*64))[i4] = ((const float4*)(g_q + (size_t)row*64))[i4];
    }
    __syncthreads();

    /* phase 1: scores for rows m = mbase..mbase+4, chunks < nc */
    float sc[5][5];
    #pragma unroll
    for (int k = 0; k < 5; ++k)
        #pragma unroll
        for (int c = 0; c < 5; ++c) sc[k][c] = 0.0f;

    switch (nc) {
        case 1: score_nc<1>(sKt, sQ, mbase, lane, sc); break;
        case 2: score_nc<2>(sKt, sQ, mbase, lane, sc); break;
        case 3: score_nc<3>(sKt, sQ, mbase, lane, sc); break;
        case 4: score_nc<4>(sKt, sQ, mbase, lane, sc); break;
        default: score_nc<5>(sKt, sQ, mbase, lane, sc); break;
    }

    /* softmax per row (s <= t), write attn weights (zeros beyond t) */
    #pragma unroll
    for (int k = 0; k < 5; ++k) {
        const int t = quad + 4*(mbase + k);
        float mval = -3.4e38f;
        #pragma unroll
        for (int c = 0; c < 5; ++c) {
            int s = c*32 + lane;
            if (c < nc && s <= t) mval = fmaxf(mval, sc[k][c]);
        }
        #pragma unroll
        for (int o = 16; o; o >>= 1) mval = fmaxf(mval, __shfl_xor_sync(0xffffffffu, mval, o));
        float sum = 0.0f;
        #pragma unroll
        for (int c = 0; c < 5; ++c) {
            int s = c*32 + lane;
            float p = (c < nc && s <= t) ? expf(sc[k][c] - mval) : 0.0f;
            sc[k][c] = p;
            sum += p;
        }
        #pragma unroll
        for (int o = 16; o; o >>= 1) sum += __shfl_xor_sync(0xffffffffu, sum, o);
        float inv = 1.0f / sum;
        float* arow = attnOut + (size_t)(part*160 + t)*160;
        #pragma unroll
        for (int c = 0; c < 5; ++c) {
            if (c < nc) {
                sc[k][c] *= inv;
                arow[c*32 + lane] = sc[k][c];
            } else {
                arow[c*32 + lane] = 0.0f;
            }
        }
    }

    __syncthreads();   /* all warps done reading sKt */

    #pragma unroll
    for (int k = 0; k < 5; ++k) {
        #pragma unroll
        for (int c = 0; c < 5; ++c)
            if (c < nc) sA[(mbase+k)*160 + c*32 + lane] = sc[k][c];
    }
    __syncwarp();

    /* phase 2: Z = A @ V up to this warp's tmax */
    const float2* sV2 = (const float2*)sV;
    float2 acc[5];
    #pragma unroll
    for (int k = 0; k < 5; ++k) acc[k] = make_float2(0.f, 0.f);

    const int send = (tmax + 4) & ~3;
    for (int s = 0; s < send; s += 4) {
        float4 a[5];
        #pragma unroll
        for (int k = 0; k < 5; ++k)
            a[k] = *(const float4*)(sA + (mbase+k)*160 + s);
        float2 v0 = sV2[(s+0)*32 + lane];
        float2 v1 = sV2[(s+1)*32 + lane];
        float2 v2 = sV2[(s+2)*32 + lane];
        float2 v3 = sV2[(s+3)*32 + lane];
        #pragma unroll
        for (int k = 0; k < 5; ++k) {
            acc[k].x += a[k].x*v0.x + a[k].y*v1.x + a[k].z*v2.x + a[k].w*v3.x;
            acc[k].y += a[k].x*v0.y + a[k].y*v1.y + a[k].z*v2.y + a[k].w*v3.y;
        }
    }
    #pragma unroll
    for (int k = 0; k < 5; ++k) {
        const int t = quad + 4*(mbase + k);
        size_t n = (size_t)part*160 + t;
        ((float2*)(g_z + n*64))[lane] = acc[k];
    }
}

/* ------------------------------------------------------------------ */
/* K3: persistent epilogue. Wo(FFMA 4x4) + merged LN, FFN1 (f32x2),   */
/* FFN2 (FFMA 4x4 K-split) + merged LN2/outputs. 5 bars/tile.         */
/* ------------------------------------------------------------------ */
__global__ void __launch_bounds__(512) k_epi(
    const float* __restrict__ Wo, const float* __restrict__ bo,
    const float* __restrict__ ln1g, const float* __restrict__ ln1b,
    const float* __restrict__ W1, const float* __restrict__ b1,
    const float* __restrict__ W2, const float* __restrict__ b2,
    const float* __restrict__ ln2g, const float* __restrict__ ln2b,
    const float* __restrict__ Wf, const float* __restrict__ bf,
    float* __restrict__ outR, float* __restrict__ outP, float* __restrict__ outP2)
{
    extern __shared__ float sm[];
    float* sWo = sm;            /* 4096  */
    float* sW1 = sWo + 4096;    /* 16384 */
    float* sW2 = sW1 + 16384;   /* 16384 */
    float* sC  = sW2 + 16384;   /* 704: bo|b1|b2|l1g|l1b|l2g|l2b|Wf */
    float* sO1 = sC  + 704;     /* 32 x 64 = 2048 */
    float* sH  = sO1 + 2048;    /* 8192: Wo partials (4x2048), then FFN1 out */
    float* sP  = sH  + 8192;    /* 4096: FFN2 partials (2x2048) */

    const int tid = threadIdx.x, w = tid >> 5, lane = tid & 31;

    for (int i = tid; i < 1024; i += 512) ((float4*)sWo)[i] = ((const float4*)Wo)[i];
    for (int i = tid; i < 4096; i += 512) {
        ((float4*)sW1)[i] = ((const float4*)W1)[i];
        ((float4*)sW2)[i] = ((const float4*)W2)[i];
    }
    if (tid < 64) {
        sC[tid]     = bo[tid];
        sC[320+tid] = b2[tid];
        sC[384+tid] = ln1g[tid];
        sC[448+tid] = ln1b[tid];
        sC[512+tid] = ln2g[tid];
        sC[576+tid] = ln2b[tid];
        sC[640+tid] = Wf[tid];
    }
    if (tid < 256) sC[64 + tid] = b1[tid];
    const float bfv = bf[0];
    __syncthreads();

    const int row = tid >> 4;       /* 0..31 for reduce/LN stages */
    const int c4  = tid & 15;

    for (int tile = blockIdx.x; tile < NROW/32; tile += gridDim.x) {
        const int row0 = tile * 32;

        /* ---- (1) Wo: 4-way K-split FFMA, partials -> sH ---- */
        {
            const int isp = tid >> 7;
            const int t1  = tid & 127;
            const int cq  = t1 & 15;
            const int rq  = t1 >> 4;
            float4 acc0 = {0,0,0,0}, acc1 = {0,0,0,0}, acc2 = {0,0,0,0}, acc3 = {0,0,0,0};
            #pragma unroll
            for (int i4 = isp*4; i4 < isp*4 + 4; ++i4) {
                float4 w0 = ((const float4*)(sWo + (i4*4+0)*64))[cq];
                float4 w1 = ((const float4*)(sWo + (i4*4+1)*64))[cq];
                float4 w2 = ((const float4*)(sWo + (i4*4+2)*64))[cq];
                float4 w3 = ((const float4*)(sWo + (i4*4+3)*64))[cq];
                float4 a0 = ((const float4*)(g_z + (size_t)(row0 + 4*rq+0)*64))[i4];
                float4 a1 = ((const float4*)(g_z + (size_t)(row0 + 4*rq+1)*64))[i4];
                float4 a2 = ((const float4*)(g_z + (size_t)(row0 + 4*rq+2)*64))[i4];
                float4 a3 = ((const float4*)(g_z + (size_t)(row0 + 4*rq+3)*64))[i4];
                fma4(acc0, a0.x, w0); fma4(acc0, a0.y, w1); fma4(acc0, a0.z, w2); fma4(acc0, a0.w, w3);
                fma4(acc1, a1.x, w0); fma4(acc1, a1.y, w1); fma4(acc1, a1.z, w2); fma4(acc1, a1.w, w3);
                fma4(acc2, a2.x, w0); fma4(acc2, a2.y, w1); fma4(acc2, a2.z, w2); fma4(acc2, a2.w, w3);
                fma4(acc3, a3.x, w0); fma4(acc3, a3.y, w1); fma4(acc3, a3.z, w2); fma4(acc3, a3.w, w3);
            }
            float4* dst = (float4*)(sH + isp*2048);
            dst[(4*rq+0)*16 + cq] = acc0;
            dst[(4*rq+1)*16 + cq] = acc1;
            dst[(4*rq+2)*16 + cq] = acc2;
            dst[(4*rq+3)*16 + cq] = acc3;
        }
        __syncthreads();

        /* ---- (2) reduce + bias + residual + LN1 -> sO1 (merged) ---- */
        {
            const float4* p = (const float4*)sH;
            float4 v = p[tid];
            float4 v1 = p[512 + tid], v2 = p[1024 + tid], v3 = p[1536 + tid];
            float4 b = ((const float4*)sC)[c4];
            float4 rx = ((const float4*)(g_x + (size_t)(row0 + row)*64))[c4];
            v.x += v1.x + v2.x + v3.x + b.x + rx.x;
            v.y += v1.y + v2.y + v3.y + b.y + rx.y;
            v.z += v1.z + v2.z + v3.z + b.z + rx.z;
            v.w += v1.w + v2.w + v3.w + b.w + rx.w;
            float s = v.x + v.y + v.z + v.w;
            #pragma unroll
            for (int o = 8; o; o >>= 1) s += __shfl_xor_sync(0xffffffffu, s, o);
            float mu = s * (1.0f/64.0f);
            float4 d = {v.x-mu, v.y-mu, v.z-mu, v.w-mu};
            float q = d.x*d.x + d.y*d.y + d.z*d.z + d.w*d.w;
            #pragma unroll
            for (int o = 8; o; o >>= 1) q += __shfl_xor_sync(0xffffffffu, q, o);
            float is = rsqrtf(q * (1.0f/64.0f) + 1e-6f);
            float4 g = ((const float4*)(sC + 384))[c4];
            float4 bb = ((const float4*)(sC + 448))[c4];
            float4 o1 = {g.x*d.x*is + bb.x, g.y*d.y*is + bb.y,
                         g.z*d.z*is + bb.z, g.w*d.w*is + bb.w};
            ((float4*)sO1)[tid] = o1;
        }
        __syncthreads();

        /* ---- (3) FFN1 with packed f32x2: 4 warps, 8 rows x 256 cols ---- */
        if (w < 4) {
            u64t acc[8][4];
            #pragma unroll
            for (int rr = 0; rr < 8; ++rr)
                #pragma unroll
                for (int p = 0; p < 4; ++p) acc[rr][p] = 0ull;
            #pragma unroll 2
            for (int i = 0; i < 64; ++i) {
                const ulonglong2* wp = (const ulonglong2*)(sW1 + i*256 + lane*8);
                ulonglong2 wA = wp[0];
                ulonglong2 wB = wp[1];
                #pragma unroll
                for (int rr = 0; rr < 8; ++rr) {
                    u64t d = dup2(sO1[(8*w + rr)*64 + i]);
                    fma2p(acc[rr][0], d, wA.x);
                    fma2p(acc[rr][1], d, wA.y);
                    fma2p(acc[rr][2], d, wB.x);
                    fma2p(acc[rr][3], d, wB.y);
                }
            }
            #pragma unroll
            for (int rr = 0; rr < 8; ++rr) {
                float v[8];
                #pragma unroll
                for (int p = 0; p < 4; ++p) {
                    float lo, hi;
                    unpack2(lo, hi, acc[rr][p]);
                    v[2*p]   = fmaxf(lo + sC[64 + lane*8 + 2*p],     0.0f);
                    v[2*p+1] = fmaxf(hi + sC[64 + lane*8 + 2*p + 1], 0.0f);
                }
                float4* dst = (float4*)(sH + (8*w + rr)*256 + lane*8);
                dst[0] = make_float4(v[0], v[1], v[2], v[3]);
                dst[1] = make_float4(v[4], v[5], v[6], v[7]);
            }
        }
        __syncthreads();

        /* ---- (4) FFN2: 2-way K-split FFMA, partials -> sP ---- */
        {
            const int isp = tid >> 8;
            const int t2  = tid & 255;
            const int cq  = t2 & 15;
            const int rq  = t2 >> 4;
            float4 acc0 = {0,0,0,0}, acc1 = {0,0,0,0};
            #pragma unroll 4
            for (int i4 = isp*32; i4 < isp*32 + 32; ++i4) {
                float4 w0 = ((const float4*)(sW2 + (i4*4+0)*64))[cq];
                float4 w1 = ((const float4*)(sW2 + (i4*4+1)*64))[cq];
                float4 w2 = ((const float4*)(sW2 + (i4*4+2)*64))[cq];
                float4 w3 = ((const float4*)(sW2 + (i4*4+3)*64))[cq];
                float4 a0 = ((const float4*)(sH + (2*rq+0)*256))[i4];
                float4 a1 = ((const float4*)(sH + (2*rq+1)*256))[i4];
                fma4(acc0, a0.x, w0); fma4(acc0, a0.y, w1); fma4(acc0, a0.z, w2); fma4(acc0, a0.w, w3);
                fma4(acc1, a1.x, w0); fma4(acc1, a1.y, w1); fma4(acc1, a1.z, w2); fma4(acc1, a1.w, w3);
            }
            float4* dst = (float4*)(sP + isp*2048);
            dst[(2*rq+0)*16 + cq] = acc0;
            dst[(2*rq+1)*16 + cq] = acc1;
        }
        __syncthreads();

        /* ---- (5) reduce + bias + residual + LN2 + R + pred (merged) ---- */
        {
            const float4* p = (const float4*)sP;
            float4 v = p[tid];
            float4 v1 = p[512 + tid];
            float4 b = ((const float4*)(sC + 320))[c4];
            float4 rs = ((const float4*)sO1)[tid];
            v.x += v1.x + b.x + rs.x;
            v.y += v1.y + b.y + rs.y;
            v.z += v1.z + b.z + rs.z;
            v.w += v1.w + b.w + rs.w;
            float s = v.x + v.y + v.z + v.w;
            #pragma unroll
            for (int o = 8; o; o >>= 1) s += __shfl_xor_sync(0xffffffffu, s, o);
            float mu = s * (1.0f/64.0f);
            float4 d = {v.x-mu, v.y-mu, v.z-mu, v.w-mu};
            float q = d.x*d.x + d.y*d.y + d.z*d.z + d.w*d.w;
            #pragma unroll
            for (int o = 8; o; o >>= 1) q += __shfl_xor_sync(0xffffffffu, q, o);
            float is = rsqrtf(q * (1.0f/64.0f) + 1e-6f);
            float4 g = ((const float4*)(sC + 512))[c4];
            float4 bb = ((const float4*)(sC + 576))[c4];
            float4 rv = {g.x*d.x*is + bb.x, g.y*d.y*is + bb.y,
                         g.z*d.z*is + bb.z, g.w*d.w*is + bb.w};
            const size_t n = (size_t)row0 + row;
            ((float4*)(outR + n*64))[c4] = rv;
            float4 wf = ((const float4*)(sC + 640))[c4];
            float pp = rv.x*wf.x + rv.y*wf.y + rv.z*wf.z + rv.w*wf.w;
            #pragma unroll
            for (int o = 8; o; o >>= 1) pp += __shfl_xor_sync(0xffffffffu, pp, o);
            if (c4 == 0) {
                float pv = pp + bfv;
                outP[n]  = pv;
                outP2[n] = pv;
            }
        }
        __syncthreads();
    }
}

/* ------------------------------------------------------------------ */
extern "C" void kernel_launch(void* const* d_in, const int* in_sizes, int n_in,
                              void* d_out, int out_size)
{
    (void)in_sizes; (void)n_in; (void)out_size;
    const float* inputs = (const float*)d_in[0];
    const float* Wp  = (const float*)d_in[2];
    const float* bp  = (const float*)d_in[3];
    const float* Wq  = (const float*)d_in[4];
    const float* bq  = (const float*)d_in[5];
    const float* Wk  = (const float*)d_in[6];
    const float* bk  = (const float*)d_in[7];
    const float* Wv  = (const float*)d_in[8];
    const float* bv  = (const float*)d_in[9];
    const float* Wo  = (const float*)d_in[10];
    const float* bo  = (const float*)d_in[11];
    const float* l1g = (const float*)d_in[12];
    const float* l1b = (const float*)d_in[13];
    const float* W1  = (const float*)d_in[14];
    const float* b1  = (const float*)d_in[15];
    const float* W2  = (const float*)d_in[16];
    const float* b2  = (const float*)d_in[17];
    const float* l2g = (const float*)d_in[18];
    const float* l2b = (const float*)d_in[19];
    const float* Wf  = (const float*)d_in[20];
    const float* bf  = (const float*)d_in[21];
    float* out = (float*)d_out;

    const size_t sm1 = (size_t)(2816 + 256 + 1408 + 4096) * 4;                  /* ~34 KB  */
    const size_t sm2 = (size_t)(10304 + 10240 + 2560) * 4;                      /* ~92 KB  */
    const size_t sm3 = (size_t)(4096 + 16384 + 16384 + 704 + 2048 + 8192 + 4096) * 4; /* ~203 KB */

    cudaFuncSetAttribute(k_qkv,  cudaFuncAttributeMaxDynamicSharedMemorySize, (int)sm1);
    cudaFuncSetAttribute(k_attn, cudaFuncAttributeMaxDynamicSharedMemorySize, (int)sm2);
    cudaFuncSetAttribute(k_epi,  cudaFuncAttributeMaxDynamicSharedMemorySize, (int)sm3);

    k_qkv<<<NROW/128, 512, sm1>>>(inputs, Wp, bp, Wq, bq, Wk, bk, Wv, bv,
                                  out + OFF_K, out + OFF_V);
    k_attn<<<NPART*4, 256, sm2>>>(out + OFF_K, out + OFF_V, out + OFF_ATTN);
    k_epi<<<148, 512, sm3>>>(Wo, bo, l1g, l1b, W1, b1, W2, b2, l2g, l2b, Wf, bf,
                             out + OFF_R, out + OFF_PRED, out + OFF_PRED2);
}